// round 1
// baseline (speedup 1.0000x reference)
#include <cuda_runtime.h>
#include <cuda_bf16.h>
#include <cstdint>

// Problem constants
#define N_ENT    100000
#define N_REL    250000
#define N_TRIG   50000
#define N_ARGS   250000
#define ENT_DIM  288
#define REL_R    256
#define RTYPE_DIM 32
#define ROLE_DIM 256
#define ARG_DIM  576          // 256 + 32 + 288
#define KDIM     1152         // 2 * ARG_DIM (in-slot | out-slot)
#define OUT_COLS 544          // ENT_DIM + ROLE_DIM

// Scratch: per-trigger x-space accumulators [N_TRIG][1152] (in: k<576, out: k>=576)
__device__ float g_X[(size_t)N_TRIG * KDIM];      // 230.4 MB
// Concatenated weights [1152][256]: rows 0..575 = W_in, 576..1151 = W_out
__device__ float g_W[KDIM * ROLE_DIM];            // 1.18 MB

// ---------------------------------------------------------------------------
// Vectorized global reduction (sm_90+): 4 floats per red op
// ---------------------------------------------------------------------------
__device__ __forceinline__ void red4(float* p, float4 v) {
    asm volatile("red.global.add.v4.f32 [%0], {%1,%2,%3,%4};"
                 :: "l"(p), "f"(v.x), "f"(v.y), "f"(v.z), "f"(v.w)
                 : "memory");
}

// ---------------------------------------------------------------------------
// Concatenate W_in | W_out into g_W
// ---------------------------------------------------------------------------
__global__ void wcat_kernel(const float* __restrict__ Win,
                            const float* __restrict__ Wout) {
    int i = blockIdx.x * blockDim.x + threadIdx.x;
    if (i < ARG_DIM * ROLE_DIM) {
        g_W[i] = Win[i];
        g_W[ARG_DIM * ROLE_DIM + i] = Wout[i];
    }
}

// ---------------------------------------------------------------------------
// Scatter: one warp per argument. Gather x = [rel | rtype | ent] (576 floats
// = 144 float4 chunks) and red.add into g_X[trig][slot].
// ---------------------------------------------------------------------------
__global__ void scatter_kernel(const float* __restrict__ rel_embeds,
                               const float* __restrict__ rtype_table,
                               const float* __restrict__ ent_embeds,
                               const int*   __restrict__ rtype_ids,
                               const int*   __restrict__ arg_trig,
                               const int*   __restrict__ arg_rel,
                               const int*   __restrict__ arg_ent,
                               const int*   __restrict__ arg_is_in) {
    int warp = (blockIdx.x * blockDim.x + threadIdx.x) >> 5;
    int lane = threadIdx.x & 31;
    if (warp >= N_ARGS) return;

    int r = arg_rel[warp];
    int e = arg_ent[warp];
    int t = arg_trig[warp];
    int m = arg_is_in[warp];
    int rt = rtype_ids[r];

    const float4* relv = (const float4*)(rel_embeds  + (size_t)r  * REL_R);
    const float4* rtv  = (const float4*)(rtype_table + (size_t)rt * RTYPE_DIM);
    const float4* entv = (const float4*)(ent_embeds  + (size_t)e  * ENT_DIM);
    float* base = g_X + (size_t)t * KDIM + (m ? 0 : ARG_DIM);

    #pragma unroll
    for (int it = 0; it < 5; ++it) {
        int c = lane + it * 32;          // float4 chunk index within 576-dim x
        if (c >= 144) break;
        float4 v;
        if (c < 64)       v = relv[c];          // rel_embeds row (256 floats)
        else if (c < 72)  v = rtv[c - 64];      // rtype row (32 floats)
        else              v = entv[c - 72];     // ent row (288 floats)
        red4(base + c * 4, v);
    }
}

// ---------------------------------------------------------------------------
// GEMM: C[50000,256] = g_X[50000,1152] @ g_W[1152,256]
// 128x128 CTA tile, BK=16, 256 threads, 8x8 per-thread register tile.
// Result written directly into d_out columns [288, 544).
// ---------------------------------------------------------------------------
#define BM 128
#define BN 128
#define BK 16

__global__ __launch_bounds__(256)
void gemm_kernel(float* __restrict__ out) {
    __shared__ float As[BK][BM + 4];   // transposed A tile, padded (2-way max)
    __shared__ float Bs[BK][BN];

    int m0 = blockIdx.x * BM;
    int n0 = blockIdx.y * BN;
    int tid = threadIdx.x;
    int tx = tid & 15;        // 0..15 -> 8 output cols each
    int ty = tid >> 4;        // 0..15 -> 8 output rows each

    float acc[8][8] = {};

    int a_row = tid >> 2;              // 0..63
    int a_c4  = (tid & 3) << 2;        // 0,4,8,12
    int b_row = tid >> 5;              // 0..7
    int b_c4  = (tid & 31) << 2;       // 0..124

    for (int k0 = 0; k0 < KDIM; k0 += BK) {
        // Load A tile (128 rows x 16 k), store transposed
        #pragma unroll
        for (int rr = 0; rr < 2; rr++) {
            int r = a_row + rr * 64;
            int gm = m0 + r;
            float4 v = make_float4(0.f, 0.f, 0.f, 0.f);
            if (gm < N_TRIG)
                v = *(const float4*)(g_X + (size_t)gm * KDIM + k0 + a_c4);
            As[a_c4 + 0][r] = v.x;
            As[a_c4 + 1][r] = v.y;
            As[a_c4 + 2][r] = v.z;
            As[a_c4 + 3][r] = v.w;
        }
        // Load B tile (16 k x 128 cols)
        #pragma unroll
        for (int rr = 0; rr < 2; rr++) {
            int kk = b_row + rr * 8;
            float4 v = *(const float4*)(g_W + (size_t)(k0 + kk) * ROLE_DIM + n0 + b_c4);
            *(float4*)(&Bs[kk][b_c4]) = v;
        }
        __syncthreads();

        #pragma unroll
        for (int k = 0; k < BK; k++) {
            float a[8], b[8];
            *(float4*)(a)     = *(const float4*)(&As[k][ty * 8]);
            *(float4*)(a + 4) = *(const float4*)(&As[k][ty * 8 + 4]);
            *(float4*)(b)     = *(const float4*)(&Bs[k][tx * 8]);
            *(float4*)(b + 4) = *(const float4*)(&Bs[k][tx * 8 + 4]);
            #pragma unroll
            for (int i = 0; i < 8; i++)
                #pragma unroll
                for (int j = 0; j < 8; j++)
                    acc[i][j] += a[i] * b[j];
        }
        __syncthreads();
    }

    // Epilogue: write into out[gm][288 + n]
    #pragma unroll
    for (int i = 0; i < 8; i++) {
        int gm = m0 + ty * 8 + i;
        if (gm < N_TRIG) {
            float* o = out + (size_t)gm * OUT_COLS + ENT_DIM + n0 + tx * 8;
            *(float4*)(o)     = *(float4*)(&acc[i][0]);
            *(float4*)(o + 4) = *(float4*)(&acc[i][4]);
        }
    }
}

// ---------------------------------------------------------------------------
// Copy trigger entity embeddings into out columns [0, 288). One warp/trigger.
// ---------------------------------------------------------------------------
__global__ void trig_copy_kernel(const float* __restrict__ ent_embeds,
                                 const int*   __restrict__ trig_ent_id,
                                 float* __restrict__ out) {
    int warp = (blockIdx.x * blockDim.x + threadIdx.x) >> 5;
    int lane = threadIdx.x & 31;
    if (warp >= N_TRIG) return;
    const float4* src = (const float4*)(ent_embeds + (size_t)trig_ent_id[warp] * ENT_DIM);
    float4* dst = (float4*)(out + (size_t)warp * OUT_COLS);
    #pragma unroll
    for (int it = 0; it < 3; ++it) {
        int c = lane + it * 32;
        if (c < ENT_DIM / 4) dst[c] = src[c];
    }
}

// ---------------------------------------------------------------------------
// Launch
// Inputs (metadata order): ent_embeds, rel_embeds, rtype_table, W_in, W_out,
//   rtype_ids, trig_ent_id, arg_trig, arg_rel, arg_ent, arg_is_in
// ---------------------------------------------------------------------------
extern "C" void kernel_launch(void* const* d_in, const int* in_sizes, int n_in,
                              void* d_out, int out_size) {
    const float* ent_embeds  = (const float*)d_in[0];
    const float* rel_embeds  = (const float*)d_in[1];
    const float* rtype_table = (const float*)d_in[2];
    const float* W_in        = (const float*)d_in[3];
    const float* W_out       = (const float*)d_in[4];
    const int*   rtype_ids   = (const int*)d_in[5];
    const int*   trig_ent_id = (const int*)d_in[6];
    const int*   arg_trig    = (const int*)d_in[7];
    const int*   arg_rel     = (const int*)d_in[8];
    const int*   arg_ent     = (const int*)d_in[9];
    const int*   arg_is_in   = (const int*)d_in[10];
    float* out = (float*)d_out;

    // Zero the x-space accumulator (must happen every replay)
    void* xptr = nullptr;
    cudaGetSymbolAddress(&xptr, g_X);
    cudaMemsetAsync(xptr, 0, (size_t)N_TRIG * KDIM * sizeof(float), 0);

    // Concatenate weights
    wcat_kernel<<<(ARG_DIM * ROLE_DIM + 255) / 256, 256>>>(W_in, W_out);

    // Scatter-accumulate x per (trigger, in/out)
    scatter_kernel<<<(N_ARGS + 7) / 8, 256>>>(rel_embeds, rtype_table, ent_embeds,
                                              rtype_ids, arg_trig, arg_rel,
                                              arg_ent, arg_is_in);

    // Dense GEMM -> out[:, 288:544]
    dim3 grid((N_TRIG + BM - 1) / BM, ROLE_DIM / BN);
    gemm_kernel<<<grid, 256>>>(out);

    // Trigger embeddings -> out[:, 0:288]
    trig_copy_kernel<<<(N_TRIG + 7) / 8, 256>>>(ent_embeds, trig_ent_id, out);
}

// round 4
// speedup vs baseline: 1.5087x; 1.5087x over previous
#include <cuda_runtime.h>
#include <cuda_bf16.h>
#include <cstdint>

// Problem constants
#define N_ENT    100000
#define N_REL    250000
#define N_TRIG   50000
#define N_ARGS   250000
#define ENT_DIM  288
#define REL_R    256
#define RTYPE_DIM 32
#define ROLE_DIM 256
#define ARG_DIM  576
#define KDIM     1152          // 2 * ARG_DIM (in-slot | out-slot)
#define OUT_COLS 544           // ENT_DIM + ROLE_DIM

#define NCHUNK   (KDIM / 32)   // 36 k-chunks of 32

// Scratch
__device__ float g_X[(size_t)N_TRIG * KDIM];            // 230.4 MB fp32 accumulators
__device__ __nv_bfloat16 g_Bth[ROLE_DIM * KDIM];        // W^T hi  [n][k], bf16
__device__ __nv_bfloat16 g_Btl[ROLE_DIM * KDIM];        // W^T lo  [n][k], bf16

// ---------------------------------------------------------------------------
// helpers
// ---------------------------------------------------------------------------
__device__ __forceinline__ void red4(float* p, float4 v) {
    asm volatile("red.global.add.v4.f32 [%0], {%1,%2,%3,%4};"
                 :: "l"(p), "f"(v.x), "f"(v.y), "f"(v.z), "f"(v.w) : "memory");
}

__device__ __forceinline__ uint32_t smem_u32(const void* p) {
    uint32_t a;
    asm("{ .reg .u64 t; cvta.to.shared.u64 t, %1; cvt.u32.u64 %0, t; }"
        : "=r"(a) : "l"(p));
    return a;
}

__device__ __forceinline__ void cp16(uint32_t dst, const void* src) {
    asm volatile("cp.async.cg.shared.global [%0], [%1], 16;" :: "r"(dst), "l"(src));
}
__device__ __forceinline__ void cp_commit() {
    asm volatile("cp.async.commit_group;" ::: "memory");
}
template <int N> __device__ __forceinline__ void cp_wait() {
    asm volatile("cp.async.wait_group %0;" :: "n"(N) : "memory");
}

// legacy tensor-core mma: m16n8k16, bf16 x bf16 -> f32 (base PTX, no 'a' feature)
#define MMA_BF16(acc, ar, br)                                                   \
    asm volatile(                                                               \
        "mma.sync.aligned.m16n8k16.row.col.f32.bf16.bf16.f32 "                  \
        "{%0,%1,%2,%3},{%4,%5,%6,%7},{%8,%9},{%0,%1,%2,%3};"                    \
        : "+f"((acc)[0]), "+f"((acc)[1]), "+f"((acc)[2]), "+f"((acc)[3])        \
        : "r"((ar)[0]), "r"((ar)[1]), "r"((ar)[2]), "r"((ar)[3]),               \
          "r"((br)[0]), "r"((br)[1]))

__device__ __forceinline__ uint32_t pack_bf16x2(float lo, float hi) {
    __nv_bfloat162 t = __floats2bfloat162_rn(lo, hi);
    return *(uint32_t*)&t;
}

// ---------------------------------------------------------------------------
// B prep: transpose + hi/lo split of [W_in ; W_out] -> g_Bth/g_Btl [n][k]
// ---------------------------------------------------------------------------
__global__ void bprep_kernel(const float* __restrict__ Win,
                             const float* __restrict__ Wout) {
    int idx = blockIdx.x * blockDim.x + threadIdx.x;
    if (idx >= KDIM * ROLE_DIM) return;
    int k = idx / ROLE_DIM;
    int n = idx % ROLE_DIM;
    float v = (k < ARG_DIM) ? Win[k * ROLE_DIM + n] : Wout[(k - ARG_DIM) * ROLE_DIM + n];
    __nv_bfloat16 h = __float2bfloat16_rn(v);
    __nv_bfloat16 l = __float2bfloat16_rn(v - __bfloat162float(h));
    g_Bth[n * KDIM + k] = h;
    g_Btl[n * KDIM + k] = l;
}

// ---------------------------------------------------------------------------
// Scatter: one warp per argument; red.add x = [rel|rtype|ent] into g_X slot
// ---------------------------------------------------------------------------
__global__ void scatter_kernel(const float* __restrict__ rel_embeds,
                               const float* __restrict__ rtype_table,
                               const float* __restrict__ ent_embeds,
                               const int*   __restrict__ rtype_ids,
                               const int*   __restrict__ arg_trig,
                               const int*   __restrict__ arg_rel,
                               const int*   __restrict__ arg_ent,
                               const int*   __restrict__ arg_is_in) {
    int warp = (blockIdx.x * blockDim.x + threadIdx.x) >> 5;
    int lane = threadIdx.x & 31;
    if (warp >= N_ARGS) return;

    int r = arg_rel[warp];
    int e = arg_ent[warp];
    int t = arg_trig[warp];
    int m = arg_is_in[warp];
    int rt = rtype_ids[r];

    const float4* relv = (const float4*)(rel_embeds  + (size_t)r  * REL_R);
    const float4* rtv  = (const float4*)(rtype_table + (size_t)rt * RTYPE_DIM);
    const float4* entv = (const float4*)(ent_embeds  + (size_t)e  * ENT_DIM);
    float* base = g_X + (size_t)t * KDIM + (m ? 0 : ARG_DIM);

    #pragma unroll
    for (int it = 0; it < 5; ++it) {
        int c = lane + it * 32;
        if (c >= 144) break;
        float4 v;
        if (c < 64)       v = relv[c];
        else if (c < 72)  v = rtv[c - 64];
        else              v = entv[c - 72];
        red4(base + c * 4, v);
    }
}

// ---------------------------------------------------------------------------
// mma.sync GEMM: out[:,288:544] = X[50000,1152] @ Wcat[1152,256]
// bf16 hi/lo 3-term split. CTA tile 128x128, K-chunk 32, double-buffered.
// SMEM stage layout (bytes): Ah@0, Al@10240, Bh@20480, Bl@30720; stride 40960.
// Rows padded to 40 bf16 (80 B) for conflict-free frag LDS.
// ---------------------------------------------------------------------------
#define STG_STRIDE 40960
#define OFF_AL 10240
#define OFF_BH 20480
#define OFF_BL 30720
#define GSMEM  (2 * STG_STRIDE)

__global__ __launch_bounds__(256)
void gemm_mma_kernel(float* __restrict__ out) {
    extern __shared__ char sm[];
    const uint32_t smb = smem_u32(sm);
    const int tid = threadIdx.x;
    const int lid = tid & 31;
    const int wid = tid >> 5;
    const int m0 = blockIdx.x * 128;
    const int n0 = blockIdx.y * 128;
    const int wm = (wid >> 2) * 64;        // warp m offset (0 or 64)
    const int wn = (wid & 3) * 32;         // warp n offset (0,32,64,96)
    const int g  = lid >> 2;               // 0..7
    const int kp = (lid & 3) * 2;          // 0,2,4,6

    // A global-load mapping: 2 threads per row, 16 k each
    const int arow = tid >> 1;             // 0..127
    const int akh  = (tid & 1) * 16;       // 0 or 16
    const int gm   = m0 + arow;
    const float* asrc = g_X + (size_t)gm * KDIM + akh;

    float areg[16];
    float acc[4][4][4];
    #pragma unroll
    for (int a = 0; a < 4; a++)
        #pragma unroll
        for (int b = 0; b < 4; b++)
            #pragma unroll
            for (int c = 0; c < 4; c++) acc[a][b][c] = 0.f;

    // ---- helpers (lambdas) ----
    auto ldgA = [&](int c) {
        if (gm < N_TRIG) {
            const float4* s = (const float4*)(asrc + c * 32);
            #pragma unroll
            for (int j = 0; j < 4; j++) {
                float4 v = s[j];
                areg[4*j+0] = v.x; areg[4*j+1] = v.y;
                areg[4*j+2] = v.z; areg[4*j+3] = v.w;
            }
        } else {
            #pragma unroll
            for (int j = 0; j < 16; j++) areg[j] = 0.f;
        }
    };
    auto stsA = [&](int p) {
        uint32_t hh[8], ll[8];
        #pragma unroll
        for (int j = 0; j < 8; j++) {
            float x0 = areg[2*j], x1 = areg[2*j+1];
            __nv_bfloat16 h0 = __float2bfloat16_rn(x0);
            __nv_bfloat16 h1 = __float2bfloat16_rn(x1);
            float l0 = x0 - __bfloat162float(h0);
            float l1 = x1 - __bfloat162float(h1);
            hh[j] = ((uint32_t)*(uint16_t*)&h0) | (((uint32_t)*(uint16_t*)&h1) << 16);
            __nv_bfloat16 lo0 = __float2bfloat16_rn(l0);
            __nv_bfloat16 lo1 = __float2bfloat16_rn(l1);
            ll[j] = ((uint32_t)*(uint16_t*)&lo0) | (((uint32_t)*(uint16_t*)&lo1) << 16);
        }
        char* base = sm + p * STG_STRIDE + arow * 80 + akh * 2;
        *(uint4*)(base)               = *(uint4*)(hh);
        *(uint4*)(base + 16)          = *(uint4*)(hh + 4);
        *(uint4*)(base + OFF_AL)      = *(uint4*)(ll);
        *(uint4*)(base + OFF_AL + 16) = *(uint4*)(ll + 4);
    };
    auto cpB = [&](int c, int p) {
        #pragma unroll
        for (int u = 0; u < 2; u++) {
            int idx = tid * 2 + u;
            int row = idx >> 2, seg = idx & 3;
            const __nv_bfloat16* sh = g_Bth + (size_t)(n0 + row) * KDIM + c * 32 + seg * 8;
            const __nv_bfloat16* sl = g_Btl + (size_t)(n0 + row) * KDIM + c * 32 + seg * 8;
            uint32_t d = smb + p * STG_STRIDE + OFF_BH + row * 80 + seg * 16;
            cp16(d, sh);
            cp16(d + (OFF_BL - OFF_BH), sl);
        }
        cp_commit();
    };
    auto compute = [&](int p, int ks) {
        const char* base = sm + p * STG_STRIDE;
        uint32_t ah[4][4], al[4][4];
        #pragma unroll
        for (int mf = 0; mf < 4; mf++) {
            int r0 = (wm + mf * 16 + g) * 80 + (ks + kp) * 2;
            int r1 = r0 + 8 * 80;
            ah[mf][0] = *(const uint32_t*)(base + r0);
            ah[mf][1] = *(const uint32_t*)(base + r1);
            ah[mf][2] = *(const uint32_t*)(base + r0 + 16);
            ah[mf][3] = *(const uint32_t*)(base + r1 + 16);
            al[mf][0] = *(const uint32_t*)(base + OFF_AL + r0);
            al[mf][1] = *(const uint32_t*)(base + OFF_AL + r1);
            al[mf][2] = *(const uint32_t*)(base + OFF_AL + r0 + 16);
            al[mf][3] = *(const uint32_t*)(base + OFF_AL + r1 + 16);
        }
        #pragma unroll
        for (int nf = 0; nf < 4; nf++) {
            int b0 = (wn + nf * 8 + g) * 80 + (ks + kp) * 2;
            uint32_t bh[2], bl[2];
            bh[0] = *(const uint32_t*)(base + OFF_BH + b0);
            bh[1] = *(const uint32_t*)(base + OFF_BH + b0 + 16);
            bl[0] = *(const uint32_t*)(base + OFF_BL + b0);
            bl[1] = *(const uint32_t*)(base + OFF_BL + b0 + 16);
            #pragma unroll
            for (int mf = 0; mf < 4; mf++) {
                MMA_BF16(acc[mf][nf], ah[mf], bh);
                MMA_BF16(acc[mf][nf], ah[mf], bl);
                MMA_BF16(acc[mf][nf], al[mf], bh);
            }
        }
    };

    // ---- prologue ----
    ldgA(0);
    cpB(0, 0);
    stsA(0);

    // ---- mainloop ----
    for (int i = 0; i < NCHUNK; i++) {
        int p = i & 1;
        if (i + 1 < NCHUNK) ldgA(i + 1);
        cp_wait<0>();
        __syncthreads();
        if (i + 1 < NCHUNK) cpB(i + 1, p ^ 1);
        compute(p, 0);
        if (i + 1 < NCHUNK) stsA(p ^ 1);
        compute(p, 16);
    }

    // ---- epilogue ----
    #pragma unroll
    for (int mf = 0; mf < 4; mf++) {
        int r = m0 + wm + mf * 16 + g;
        #pragma unroll
        for (int nf = 0; nf < 4; nf++) {
            int cc = ENT_DIM + n0 + wn + nf * 8 + kp;
            if (r < N_TRIG)
                *(float2*)(out + (size_t)r * OUT_COLS + cc) =
                    make_float2(acc[mf][nf][0], acc[mf][nf][1]);
            if (r + 8 < N_TRIG)
                *(float2*)(out + (size_t)(r + 8) * OUT_COLS + cc) =
                    make_float2(acc[mf][nf][2], acc[mf][nf][3]);
        }
    }
}

// ---------------------------------------------------------------------------
// Trigger entity embeddings -> out[:, 0:288). One warp per trigger.
// ---------------------------------------------------------------------------
__global__ void trig_copy_kernel(const float* __restrict__ ent_embeds,
                                 const int*   __restrict__ trig_ent_id,
                                 float* __restrict__ out) {
    int warp = (blockIdx.x * blockDim.x + threadIdx.x) >> 5;
    int lane = threadIdx.x & 31;
    if (warp >= N_TRIG) return;
    const float4* src = (const float4*)(ent_embeds + (size_t)trig_ent_id[warp] * ENT_DIM);
    float4* dst = (float4*)(out + (size_t)warp * OUT_COLS);
    #pragma unroll
    for (int it = 0; it < 3; ++it) {
        int c = lane + it * 32;
        if (c < ENT_DIM / 4) dst[c] = src[c];
    }
}

// ---------------------------------------------------------------------------
// Launch
// ---------------------------------------------------------------------------
extern "C" void kernel_launch(void* const* d_in, const int* in_sizes, int n_in,
                              void* d_out, int out_size) {
    const float* ent_embeds  = (const float*)d_in[0];
    const float* rel_embeds  = (const float*)d_in[1];
    const float* rtype_table = (const float*)d_in[2];
    const float* W_in        = (const float*)d_in[3];
    const float* W_out       = (const float*)d_in[4];
    const int*   rtype_ids   = (const int*)d_in[5];
    const int*   trig_ent_id = (const int*)d_in[6];
    const int*   arg_trig    = (const int*)d_in[7];
    const int*   arg_rel     = (const int*)d_in[8];
    const int*   arg_ent     = (const int*)d_in[9];
    const int*   arg_is_in   = (const int*)d_in[10];
    float* out = (float*)d_out;

    // >48KB dynamic smem opt-in (idempotent, capture-safe; not a stream op)
    cudaFuncSetAttribute(gemm_mma_kernel,
                         cudaFuncAttributeMaxDynamicSharedMemorySize, GSMEM);

    // zero X accumulator
    void* xptr = nullptr;
    cudaGetSymbolAddress(&xptr, g_X);
    cudaMemsetAsync(xptr, 0, (size_t)N_TRIG * KDIM * sizeof(float), 0);

    // transpose + hi/lo split weights
    bprep_kernel<<<(KDIM * ROLE_DIM + 255) / 256, 256>>>(W_in, W_out);

    // scatter x-space sums per (trigger, in/out slot)
    scatter_kernel<<<(N_ARGS + 7) / 8, 256>>>(rel_embeds, rtype_table, ent_embeds,
                                              rtype_ids, arg_trig, arg_rel,
                                              arg_ent, arg_is_in);

    // tensor-core GEMM (mma.sync bf16 3-term) -> out[:, 288:544]
    dim3 grid((N_TRIG + 127) / 128, ROLE_DIM / 128);
    gemm_mma_kernel<<<grid, 256, GSMEM>>>(out);

    // trigger embeddings -> out[:, 0:288]
    trig_copy_kernel<<<(N_TRIG + 7) / 8, 256>>>(ent_embeds, trig_ent_id, out);
}

// round 5
// speedup vs baseline: 2.0479x; 1.3574x over previous
#include <cuda_runtime.h>
#include <cuda_bf16.h>
#include <cuda_fp16.h>
#include <cstdint>

// Problem constants
#define N_ENT    100000
#define N_REL    250000
#define N_TRIG   50000
#define N_ARGS   250000
#define ENT_DIM  288
#define REL_R    256
#define RTYPE_DIM 32
#define ROLE_DIM 256
#define ARG_DIM  576
#define KDIM     1152          // 2 * ARG_DIM (in-slot | out-slot)
#define OUT_COLS 544           // ENT_DIM + ROLE_DIM

#define NCHUNK   (KDIM / 32)   // 36 k-chunks of 32

// Scratch
__device__ float g_X[(size_t)N_TRIG * KDIM];     // 230.4 MB fp32 accumulators
__device__ __half g_Bth[ROLE_DIM * KDIM];        // W^T hi  [n][k], fp16
__device__ __half g_Btl[ROLE_DIM * KDIM];        // W^T lo  [n][k], fp16

// ---------------------------------------------------------------------------
// helpers
// ---------------------------------------------------------------------------
__device__ __forceinline__ void red4(float* p, float4 v) {
    asm volatile("red.global.add.v4.f32 [%0], {%1,%2,%3,%4};"
                 :: "l"(p), "f"(v.x), "f"(v.y), "f"(v.z), "f"(v.w) : "memory");
}

__device__ __forceinline__ uint32_t smem_u32(const void* p) {
    uint32_t a;
    asm("{ .reg .u64 t; cvta.to.shared.u64 t, %1; cvt.u32.u64 %0, t; }"
        : "=r"(a) : "l"(p));
    return a;
}

__device__ __forceinline__ void cp16(uint32_t dst, const void* src) {
    asm volatile("cp.async.cg.shared.global [%0], [%1], 16;" :: "r"(dst), "l"(src));
}
__device__ __forceinline__ void cp_commit() {
    asm volatile("cp.async.commit_group;" ::: "memory");
}
template <int N> __device__ __forceinline__ void cp_wait() {
    asm volatile("cp.async.wait_group %0;" :: "n"(N) : "memory");
}

// fp16 tensor-core mma: m16n8k16 f32 accum (base PTX, sm_80+)
#define MMA_F16(acc, ar, br)                                                    \
    asm volatile(                                                               \
        "mma.sync.aligned.m16n8k16.row.col.f32.f16.f16.f32 "                    \
        "{%0,%1,%2,%3},{%4,%5,%6,%7},{%8,%9},{%0,%1,%2,%3};"                    \
        : "+f"((acc)[0]), "+f"((acc)[1]), "+f"((acc)[2]), "+f"((acc)[3])        \
        : "r"((ar)[0]), "r"((ar)[1]), "r"((ar)[2]), "r"((ar)[3]),               \
          "r"((br)[0]), "r"((br)[1]))

#define LDMATRIX_X4(r, addr)                                                    \
    asm volatile("ldmatrix.sync.aligned.m8n8.x4.shared.b16 {%0,%1,%2,%3}, [%4];"\
                 : "=r"((r)[0]), "=r"((r)[1]), "=r"((r)[2]), "=r"((r)[3])       \
                 : "r"(addr))

#define LDMATRIX_X2(r, addr)                                                    \
    asm volatile("ldmatrix.sync.aligned.m8n8.x2.shared.b16 {%0,%1}, [%2];"      \
                 : "=r"((r)[0]), "=r"((r)[1]) : "r"(addr))

// ---------------------------------------------------------------------------
// B prep: transpose + fp16 hi/lo split of [W_in ; W_out] -> g_Bth/g_Btl [n][k]
// ---------------------------------------------------------------------------
__global__ void bprep_kernel(const float* __restrict__ Win,
                             const float* __restrict__ Wout) {
    int idx = blockIdx.x * blockDim.x + threadIdx.x;
    if (idx >= KDIM * ROLE_DIM) return;
    int k = idx / ROLE_DIM;
    int n = idx % ROLE_DIM;
    float v = (k < ARG_DIM) ? Win[k * ROLE_DIM + n] : Wout[(k - ARG_DIM) * ROLE_DIM + n];
    __half h = __float2half_rn(v);
    __half l = __float2half_rn(v - __half2float(h));
    g_Bth[n * KDIM + k] = h;
    g_Btl[n * KDIM + k] = l;
}

// ---------------------------------------------------------------------------
// Scatter: one warp per argument; red.add x = [rel|rtype|ent] into g_X slot
// ---------------------------------------------------------------------------
__global__ void scatter_kernel(const float* __restrict__ rel_embeds,
                               const float* __restrict__ rtype_table,
                               const float* __restrict__ ent_embeds,
                               const int*   __restrict__ rtype_ids,
                               const int*   __restrict__ arg_trig,
                               const int*   __restrict__ arg_rel,
                               const int*   __restrict__ arg_ent,
                               const int*   __restrict__ arg_is_in) {
    int warp = (blockIdx.x * blockDim.x + threadIdx.x) >> 5;
    int lane = threadIdx.x & 31;
    if (warp >= N_ARGS) return;

    int r = arg_rel[warp];
    int e = arg_ent[warp];
    int t = arg_trig[warp];
    int m = arg_is_in[warp];
    int rt = rtype_ids[r];

    const float4* relv = (const float4*)(rel_embeds  + (size_t)r  * REL_R);
    const float4* rtv  = (const float4*)(rtype_table + (size_t)rt * RTYPE_DIM);
    const float4* entv = (const float4*)(ent_embeds  + (size_t)e  * ENT_DIM);
    float* base = g_X + (size_t)t * KDIM + (m ? 0 : ARG_DIM);

    #pragma unroll
    for (int it = 0; it < 5; ++it) {
        int c = lane + it * 32;
        if (c >= 144) break;
        float4 v;
        if (c < 64)       v = relv[c];
        else if (c < 72)  v = rtv[c - 64];
        else              v = entv[c - 72];
        red4(base + c * 4, v);
    }
}

// ---------------------------------------------------------------------------
// mma.sync fp16 2-term GEMM: out[:,288:544] = X[50000,1152] @ Wcat[1152,256]
// X -> single fp16 (on the fly); W pre-split fp16 hi/lo.
// CTA tile 128x128, K-chunk 32, double-buffered; ldmatrix fragment loads.
// SMEM per stage (bytes): A@0 (128 rows x 80B), Bh@10240, Bl@20480; stride 30720.
// ---------------------------------------------------------------------------
#define ROWB   80
#define OFF_BH 10240
#define OFF_BL 20480
#define STG_STRIDE 30720
#define GSMEM  (2 * STG_STRIDE)

__global__ __launch_bounds__(256, 2)
void gemm_mma_kernel(float* __restrict__ out) {
    extern __shared__ char sm[];
    const uint32_t smb = smem_u32(sm);
    const int tid = threadIdx.x;
    const int lid = tid & 31;
    const int wid = tid >> 5;
    const int m0 = blockIdx.x * 128;
    const int n0 = blockIdx.y * 128;
    const int wm = (wid >> 2) * 64;        // warp m offset (0 or 64)
    const int wn = (wid & 3) * 32;         // warp n offset (0,32,64,96)
    const int g  = lid >> 2;               // 0..7
    const int kp = (lid & 3) * 2;          // 0,2,4,6

    // A global-load mapping: 2 threads per row, 16 k each
    const int arow = tid >> 1;             // 0..127
    const int akh  = (tid & 1) * 16;       // 0 or 16
    const int gm   = m0 + arow;
    const float* asrc = g_X + (size_t)gm * KDIM + akh;

    float areg[16];
    float acc[4][4][4];
    #pragma unroll
    for (int a = 0; a < 4; a++)
        #pragma unroll
        for (int b = 0; b < 4; b++)
            #pragma unroll
            for (int c = 0; c < 4; c++) acc[a][b][c] = 0.f;

    auto ldgA = [&](int c) {
        if (gm < N_TRIG) {
            const float4* s = (const float4*)(asrc + c * 32);
            #pragma unroll
            for (int j = 0; j < 4; j++) {
                float4 v = s[j];
                areg[4*j+0] = v.x; areg[4*j+1] = v.y;
                areg[4*j+2] = v.z; areg[4*j+3] = v.w;
            }
        } else {
            #pragma unroll
            for (int j = 0; j < 16; j++) areg[j] = 0.f;
        }
    };
    auto stsA = [&](int p) {
        uint32_t hh[8];
        #pragma unroll
        for (int j = 0; j < 8; j++) {
            __half2 h = __floats2half2_rn(areg[2*j], areg[2*j+1]);
            hh[j] = *(uint32_t*)&h;
        }
        char* base = sm + p * STG_STRIDE + arow * ROWB + akh * 2;
        *(uint4*)(base)      = *(uint4*)(hh);
        *(uint4*)(base + 16) = *(uint4*)(hh + 4);
    };
    auto cpB = [&](int c, int p) {
        #pragma unroll
        for (int u = 0; u < 2; u++) {
            int idx = tid * 2 + u;
            int row = idx >> 2, seg = idx & 3;
            const __half* sh = g_Bth + (size_t)(n0 + row) * KDIM + c * 32 + seg * 8;
            const __half* sl = g_Btl + (size_t)(n0 + row) * KDIM + c * 32 + seg * 8;
            uint32_t d = smb + p * STG_STRIDE + OFF_BH + row * ROWB + seg * 16;
            cp16(d, sh);
            cp16(d + (OFF_BL - OFF_BH), sl);
        }
        cp_commit();
    };
    auto compute = [&](int p, int ks) {
        const uint32_t base = smb + p * STG_STRIDE;
        // A fragments via ldmatrix.x4 (16x16 tiles)
        uint32_t a[4][4];
        #pragma unroll
        for (int mf = 0; mf < 4; mf++) {
            uint32_t addr = base + (uint32_t)(wm + mf * 16 + (lid & 15)) * ROWB
                          + ks * 2 + (lid >> 4) * 16;
            LDMATRIX_X4(a[mf], addr);
        }
        // B fragments via ldmatrix.x2 (8x16 tiles), hi and lo
        uint32_t bh[4][2], bl[4][2];
        #pragma unroll
        for (int nf = 0; nf < 4; nf++) {
            uint32_t addr = base + OFF_BH + (uint32_t)(wn + nf * 8 + (lid & 7)) * ROWB
                          + ks * 2 + ((lid >> 3) & 1) * 16;
            LDMATRIX_X2(bh[nf], addr);
            LDMATRIX_X2(bl[nf], addr + (OFF_BL - OFF_BH));
        }
        #pragma unroll
        for (int nf = 0; nf < 4; nf++)
            #pragma unroll
            for (int mf = 0; mf < 4; mf++) {
                MMA_F16(acc[mf][nf], a[mf], bh[nf]);
                MMA_F16(acc[mf][nf], a[mf], bl[nf]);
            }
    };

    // ---- prologue ----
    ldgA(0);
    cpB(0, 0);
    stsA(0);

    // ---- mainloop ----
    for (int i = 0; i < NCHUNK; i++) {
        int p = i & 1;
        if (i + 1 < NCHUNK) ldgA(i + 1);
        cp_wait<0>();
        __syncthreads();
        if (i + 1 < NCHUNK) cpB(i + 1, p ^ 1);
        compute(p, 0);
        if (i + 1 < NCHUNK) stsA(p ^ 1);
        compute(p, 16);
        // stsA wrote into the other stage; next iteration's __syncthreads orders it
    }

    // ---- epilogue ----
    #pragma unroll
    for (int mf = 0; mf < 4; mf++) {
        int r = m0 + wm + mf * 16 + g;
        #pragma unroll
        for (int nf = 0; nf < 4; nf++) {
            int cc = ENT_DIM + n0 + wn + nf * 8 + kp;
            if (r < N_TRIG)
                *(float2*)(out + (size_t)r * OUT_COLS + cc) =
                    make_float2(acc[mf][nf][0], acc[mf][nf][1]);
            if (r + 8 < N_TRIG)
                *(float2*)(out + (size_t)(r + 8) * OUT_COLS + cc) =
                    make_float2(acc[mf][nf][2], acc[mf][nf][3]);
        }
    }
}

// ---------------------------------------------------------------------------
// Trigger entity embeddings -> out[:, 0:288). One warp per trigger.
// ---------------------------------------------------------------------------
__global__ void trig_copy_kernel(const float* __restrict__ ent_embeds,
                                 const int*   __restrict__ trig_ent_id,
                                 float* __restrict__ out) {
    int warp = (blockIdx.x * blockDim.x + threadIdx.x) >> 5;
    int lane = threadIdx.x & 31;
    if (warp >= N_TRIG) return;
    const float4* src = (const float4*)(ent_embeds + (size_t)trig_ent_id[warp] * ENT_DIM);
    float4* dst = (float4*)(out + (size_t)warp * OUT_COLS);
    #pragma unroll
    for (int it = 0; it < 3; ++it) {
        int c = lane + it * 32;
        if (c < ENT_DIM / 4) dst[c] = src[c];
    }
}

// ---------------------------------------------------------------------------
// Launch  (trig_copy moved BEFORE gemm so ncu's fixed skip-count lands on gemm)
// ---------------------------------------------------------------------------
extern "C" void kernel_launch(void* const* d_in, const int* in_sizes, int n_in,
                              void* d_out, int out_size) {
    const float* ent_embeds  = (const float*)d_in[0];
    const float* rel_embeds  = (const float*)d_in[1];
    const float* rtype_table = (const float*)d_in[2];
    const float* W_in        = (const float*)d_in[3];
    const float* W_out       = (const float*)d_in[4];
    const int*   rtype_ids   = (const int*)d_in[5];
    const int*   trig_ent_id = (const int*)d_in[6];
    const int*   arg_trig    = (const int*)d_in[7];
    const int*   arg_rel     = (const int*)d_in[8];
    const int*   arg_ent     = (const int*)d_in[9];
    const int*   arg_is_in   = (const int*)d_in[10];
    float* out = (float*)d_out;

    cudaFuncSetAttribute(gemm_mma_kernel,
                         cudaFuncAttributeMaxDynamicSharedMemorySize, GSMEM);

    // zero X accumulator
    void* xptr = nullptr;
    cudaGetSymbolAddress(&xptr, g_X);
    cudaMemsetAsync(xptr, 0, (size_t)N_TRIG * KDIM * sizeof(float), 0);

    // transpose + fp16 hi/lo split weights
    bprep_kernel<<<(KDIM * ROLE_DIM + 255) / 256, 256>>>(W_in, W_out);

    // scatter x-space sums per (trigger, in/out slot)
    scatter_kernel<<<(N_ARGS + 7) / 8, 256>>>(rel_embeds, rtype_table, ent_embeds,
                                              rtype_ids, arg_trig, arg_rel,
                                              arg_ent, arg_is_in);

    // trigger embeddings -> out[:, 0:288]   (independent of gemm columns)
    trig_copy_kernel<<<(N_TRIG + 7) / 8, 256>>>(ent_embeds, trig_ent_id, out);

    // tensor-core GEMM (fp16 2-term) -> out[:, 288:544]
    dim3 grid((N_TRIG + 127) / 128, ROLE_DIM / 128);
    gemm_mma_kernel<<<grid, 256, GSMEM>>>(out);
}

// round 6
// speedup vs baseline: 3.2517x; 1.5878x over previous
#include <cuda_runtime.h>
#include <cuda_bf16.h>
#include <cuda_fp16.h>
#include <cstdint>

// Problem constants
#define N_ENT    100000
#define N_REL    250000
#define N_TRIG   50000
#define N_ARGS   250000
#define ENT_DIM  288
#define REL_R    256
#define RTYPE_DIM 32
#define ROLE_DIM 256
#define ARG_DIM  576
#define KDIM     1152          // 2 * ARG_DIM (in-slot | out-slot)
#define OUT_COLS 544           // ENT_DIM + ROLE_DIM

#define NCHUNK   (KDIM / 32)   // 36 k-chunks of 32

// Scratch (fp16 X accumulators + fp16 W^T)
__device__ __half g_Xh[(size_t)N_TRIG * KDIM];   // 115.2 MB
__device__ __half g_Bth[ROLE_DIM * KDIM];        // W^T [n][k], fp16

// ---------------------------------------------------------------------------
// helpers
// ---------------------------------------------------------------------------
__device__ __forceinline__ uint32_t smem_u32(const void* p) {
    uint32_t a;
    asm("{ .reg .u64 t; cvta.to.shared.u64 t, %1; cvt.u32.u64 %0, t; }"
        : "=r"(a) : "l"(p));
    return a;
}

// 16B vector fp16 reduction (8 halfs per op)
__device__ __forceinline__ void red_h8(__half* p, uint32_t a, uint32_t b,
                                       uint32_t c, uint32_t d) {
    asm volatile("red.global.add.noftz.v4.f16x2 [%0], {%1,%2,%3,%4};"
                 :: "l"(p), "r"(a), "r"(b), "r"(c), "r"(d) : "memory");
}

__device__ __forceinline__ void cp16(uint32_t dst, const void* src) {
    asm volatile("cp.async.cg.shared.global [%0], [%1], 16;" :: "r"(dst), "l"(src));
}
__device__ __forceinline__ void cp16_pred(uint32_t dst, const void* src, int bytes) {
    asm volatile("cp.async.cg.shared.global [%0], [%1], 16, %2;"
                 :: "r"(dst), "l"(src), "r"(bytes));
}
__device__ __forceinline__ void cp_commit() {
    asm volatile("cp.async.commit_group;" ::: "memory");
}
template <int N> __device__ __forceinline__ void cp_wait() {
    asm volatile("cp.async.wait_group %0;" :: "n"(N) : "memory");
}

// fp16 tensor-core mma: m16n8k16 f32 accum (base PTX, sm_80+)
#define MMA_F16(acc, ar, br)                                                    \
    asm volatile(                                                               \
        "mma.sync.aligned.m16n8k16.row.col.f32.f16.f16.f32 "                    \
        "{%0,%1,%2,%3},{%4,%5,%6,%7},{%8,%9},{%0,%1,%2,%3};"                    \
        : "+f"((acc)[0]), "+f"((acc)[1]), "+f"((acc)[2]), "+f"((acc)[3])        \
        : "r"((ar)[0]), "r"((ar)[1]), "r"((ar)[2]), "r"((ar)[3]),               \
          "r"((br)[0]), "r"((br)[1]))

#define LDMATRIX_X4(r, addr)                                                    \
    asm volatile("ldmatrix.sync.aligned.m8n8.x4.shared.b16 {%0,%1,%2,%3}, [%4];"\
                 : "=r"((r)[0]), "=r"((r)[1]), "=r"((r)[2]), "=r"((r)[3])       \
                 : "r"(addr))

#define LDMATRIX_X2(r, addr)                                                    \
    asm volatile("ldmatrix.sync.aligned.m8n8.x2.shared.b16 {%0,%1}, [%2];"      \
                 : "=r"((r)[0]), "=r"((r)[1]) : "r"(addr))

// ---------------------------------------------------------------------------
// B prep: transpose [W_in ; W_out] -> g_Bth [n][k] fp16
// ---------------------------------------------------------------------------
__global__ void bprep_kernel(const float* __restrict__ Win,
                             const float* __restrict__ Wout) {
    int idx = blockIdx.x * blockDim.x + threadIdx.x;
    if (idx >= KDIM * ROLE_DIM) return;
    int k = idx / ROLE_DIM;
    int n = idx % ROLE_DIM;
    float v = (k < ARG_DIM) ? Win[k * ROLE_DIM + n] : Wout[(k - ARG_DIM) * ROLE_DIM + n];
    g_Bth[n * KDIM + k] = __float2half_rn(v);
}

// ---------------------------------------------------------------------------
// Scatter: one warp per argument; fp16x8 red of x = [rel|rtype|ent] into g_Xh
// 72 chunks of 8 floats per argument.
// ---------------------------------------------------------------------------
__global__ void scatter_kernel(const float* __restrict__ rel_embeds,
                               const float* __restrict__ rtype_table,
                               const float* __restrict__ ent_embeds,
                               const int*   __restrict__ rtype_ids,
                               const int*   __restrict__ arg_trig,
                               const int*   __restrict__ arg_rel,
                               const int*   __restrict__ arg_ent,
                               const int*   __restrict__ arg_is_in) {
    int warp = (blockIdx.x * blockDim.x + threadIdx.x) >> 5;
    int lane = threadIdx.x & 31;
    if (warp >= N_ARGS) return;

    int r = arg_rel[warp];
    int e = arg_ent[warp];
    int t = arg_trig[warp];
    int m = arg_is_in[warp];
    int rt = rtype_ids[r];

    const float4* relv = (const float4*)(rel_embeds  + (size_t)r  * REL_R);
    const float4* rtv  = (const float4*)(rtype_table + (size_t)rt * RTYPE_DIM);
    const float4* entv = (const float4*)(ent_embeds  + (size_t)e  * ENT_DIM);
    __half* base = g_Xh + (size_t)t * KDIM + (m ? 0 : ARG_DIM);

    #pragma unroll
    for (int it = 0; it < 3; ++it) {
        int c = lane + it * 32;          // 8-float chunk index (0..71)
        if (c >= 72) break;
        float4 v0, v1;
        if (c < 32)       { v0 = relv[c * 2];        v1 = relv[c * 2 + 1]; }
        else if (c < 36)  { v0 = rtv[(c - 32) * 2];  v1 = rtv[(c - 32) * 2 + 1]; }
        else              { v0 = entv[(c - 36) * 2]; v1 = entv[(c - 36) * 2 + 1]; }
        __half2 h0 = __floats2half2_rn(v0.x, v0.y);
        __half2 h1 = __floats2half2_rn(v0.z, v0.w);
        __half2 h2 = __floats2half2_rn(v1.x, v1.y);
        __half2 h3 = __floats2half2_rn(v1.z, v1.w);
        red_h8(base + c * 8, *(uint32_t*)&h0, *(uint32_t*)&h1,
               *(uint32_t*)&h2, *(uint32_t*)&h3);
    }
}

// ---------------------------------------------------------------------------
// mma.sync fp16 single-term GEMM: out[:,288:544] = Xh[50000,1152] @ Wcat
// CTA tile 128x128, K-chunk 32, 3-stage cp.async pipeline, ldmatrix frags.
// SMEM per stage: A@0 (128 rows x 80B), B@10240 (128 rows x 80B); stride 20480.
// ---------------------------------------------------------------------------
#define ROWB   80
#define OFF_B  10240
#define STG_STRIDE 20480
#define NSTAGE 3
#define GSMEM  (NSTAGE * STG_STRIDE)

__global__ __launch_bounds__(256, 2)
void gemm_mma_kernel(float* __restrict__ out) {
    extern __shared__ char sm[];
    const uint32_t smb = smem_u32(sm);
    const int tid = threadIdx.x;
    const int lid = tid & 31;
    const int wid = tid >> 5;
    const int m0 = blockIdx.x * 128;
    const int n0 = blockIdx.y * 128;
    const int wm = (wid >> 2) * 64;        // warp m offset (0 or 64)
    const int wn = (wid & 3) * 32;         // warp n offset (0,32,64,96)
    const int g  = lid >> 2;               // 0..7
    const int kp = (lid & 3) * 2;          // 0,2,4,6

    // cp.async mapping: 2 ops per tensor per thread; idx over 512 = row*4+seg
    const int row0 = tid >> 1;             // via idx = tid*2+u -> row = idx>>2
    float acc[4][4][4];
    #pragma unroll
    for (int a = 0; a < 4; a++)
        #pragma unroll
        for (int b = 0; b < 4; b++)
            #pragma unroll
            for (int c = 0; c < 4; c++) acc[a][b][c] = 0.f;

    auto cpStage = [&](int c, int p) {
        uint32_t stg = smb + p * STG_STRIDE;
        #pragma unroll
        for (int u = 0; u < 2; u++) {
            int idx = tid * 2 + u;
            int row = idx >> 2, seg = idx & 3;
            // A rows (triggers)
            int gm = m0 + row;
            const __half* sa = g_Xh + (size_t)gm * KDIM + c * 32 + seg * 8;
            cp16_pred(stg + row * ROWB + seg * 16, sa, (gm < N_TRIG) ? 16 : 0);
            // B rows (n)
            const __half* sb = g_Bth + (size_t)(n0 + row) * KDIM + c * 32 + seg * 8;
            cp16(stg + OFF_B + row * ROWB + seg * 16, sb);
        }
        cp_commit();
    };

    auto compute = [&](int p) {
        const uint32_t base = smb + p * STG_STRIDE;
        #pragma unroll
        for (int ks = 0; ks < 32; ks += 16) {
            uint32_t a[4][4];
            #pragma unroll
            for (int mf = 0; mf < 4; mf++) {
                uint32_t addr = base + (uint32_t)(wm + mf * 16 + (lid & 15)) * ROWB
                              + ks * 2 + (lid >> 4) * 16;
                LDMATRIX_X4(a[mf], addr);
            }
            uint32_t bh[4][2];
            #pragma unroll
            for (int nf = 0; nf < 4; nf++) {
                uint32_t addr = base + OFF_B + (uint32_t)(wn + nf * 8 + (lid & 7)) * ROWB
                              + ks * 2 + ((lid >> 3) & 1) * 16;
                LDMATRIX_X2(bh[nf], addr);
            }
            #pragma unroll
            for (int nf = 0; nf < 4; nf++)
                #pragma unroll
                for (int mf = 0; mf < 4; mf++)
                    MMA_F16(acc[mf][nf], a[mf], bh[nf]);
        }
    };

    // ---- prologue: stages 0,1 in flight ----
    cpStage(0, 0);
    cpStage(1, 1);

    // ---- mainloop: wait(stage i) -> sync -> issue(stage i+2) -> compute(i) ----
    for (int i = 0; i < NCHUNK; i++) {
        cp_wait<1>();
        __syncthreads();
        if (i + 2 < NCHUNK) cpStage(i + 2, (i + 2) % NSTAGE);
        else                cp_commit();            // keep group count uniform
        compute(i % NSTAGE);
    }

    // ---- epilogue ----
    #pragma unroll
    for (int mf = 0; mf < 4; mf++) {
        int r = m0 + wm + mf * 16 + g;
        #pragma unroll
        for (int nf = 0; nf < 4; nf++) {
            int cc = ENT_DIM + n0 + wn + nf * 8 + kp;
            if (r < N_TRIG)
                *(float2*)(out + (size_t)r * OUT_COLS + cc) =
                    make_float2(acc[mf][nf][0], acc[mf][nf][1]);
            if (r + 8 < N_TRIG)
                *(float2*)(out + (size_t)(r + 8) * OUT_COLS + cc) =
                    make_float2(acc[mf][nf][2], acc[mf][nf][3]);
        }
    }
}

// ---------------------------------------------------------------------------
// Trigger entity embeddings -> out[:, 0:288). One warp per trigger.
// ---------------------------------------------------------------------------
__global__ void trig_copy_kernel(const float* __restrict__ ent_embeds,
                                 const int*   __restrict__ trig_ent_id,
                                 float* __restrict__ out) {
    int warp = (blockIdx.x * blockDim.x + threadIdx.x) >> 5;
    int lane = threadIdx.x & 31;
    if (warp >= N_TRIG) return;
    const float4* src = (const float4*)(ent_embeds + (size_t)trig_ent_id[warp] * ENT_DIM);
    float4* dst = (float4*)(out + (size_t)warp * OUT_COLS);
    #pragma unroll
    for (int it = 0; it < 3; ++it) {
        int c = lane + it * 32;
        if (c < ENT_DIM / 4) dst[c] = src[c];
    }
}

// ---------------------------------------------------------------------------
// Launch
// ---------------------------------------------------------------------------
extern "C" void kernel_launch(void* const* d_in, const int* in_sizes, int n_in,
                              void* d_out, int out_size) {
    const float* ent_embeds  = (const float*)d_in[0];
    const float* rel_embeds  = (const float*)d_in[1];
    const float* rtype_table = (const float*)d_in[2];
    const float* W_in        = (const float*)d_in[3];
    const float* W_out       = (const float*)d_in[4];
    const int*   rtype_ids   = (const int*)d_in[5];
    const int*   trig_ent_id = (const int*)d_in[6];
    const int*   arg_trig    = (const int*)d_in[7];
    const int*   arg_rel     = (const int*)d_in[8];
    const int*   arg_ent     = (const int*)d_in[9];
    const int*   arg_is_in   = (const int*)d_in[10];
    float* out = (float*)d_out;

    cudaFuncSetAttribute(gemm_mma_kernel,
                         cudaFuncAttributeMaxDynamicSharedMemorySize, GSMEM);

    // zero fp16 X accumulator (115 MB)
    void* xptr = nullptr;
    cudaGetSymbolAddress(&xptr, g_Xh);
    cudaMemsetAsync(xptr, 0, (size_t)N_TRIG * KDIM * sizeof(__half), 0);

    // transpose weights -> fp16
    bprep_kernel<<<(KDIM * ROLE_DIM + 255) / 256, 256>>>(W_in, W_out);

    // scatter x-space sums per (trigger, in/out slot), fp16 atomics
    scatter_kernel<<<(N_ARGS + 7) / 8, 256>>>(rel_embeds, rtype_table, ent_embeds,
                                              rtype_ids, arg_trig, arg_rel,
                                              arg_ent, arg_is_in);

    // trigger embeddings -> out[:, 0:288]
    trig_copy_kernel<<<(N_TRIG + 7) / 8, 256>>>(ent_embeds, trig_ent_id, out);

    // tensor-core GEMM (fp16 single-term) -> out[:, 288:544]
    dim3 grid((N_TRIG + 127) / 128, ROLE_DIM / 128);
    gemm_mma_kernel<<<grid, 256, GSMEM>>>(out);
}